// round 11
// baseline (speedup 1.0000x reference)
#include <cuda_runtime.h>
#include <cuda_bf16.h>
#include <cstdint>

#define B_    64
#define V_    2048
#define ENC_  128
#define T_    100
#define EMB_  256
#define DEC_  512
#define ATT_  256
#define VOC_  29
#define XDIM_ 896
#define NROW_ 413   // 256 dec_att + 128 gate + 29 pred

#define GRID_ 148
#define NTHR_ 1024
#define NBAR_ 400    // 4 barriers * 100 steps

#define KSL_  112    // K per slab (896/8)
#define NSLAB_ 8

// ---------------- scratch ----------------
__device__ __nv_bfloat16 g_enc_att_bf[(size_t)B_ * V_ * ATT_];   // 67 MB
__device__ __nv_bfloat16 g_enc_bf[(size_t)B_ * V_ * ENC_];       // 33.5 MB
__device__ float g_mean[B_ * ENC_];
__device__ float g_h[B_ * DEC_];
__device__ float g_hn[B_ * DEC_];
__device__ float g_c[B_ * DEC_];
__device__ float g_dec_att[B_ * ATT_];
__device__ float g_gate[B_ * ENC_];
__device__ float g_scores[B_ * V_];                        // holds exp(score)
__device__ float g_x[B_ * XDIM_];                          // emb in cols 0..255
__device__ float g_gates_p[NSLAB_][B_ * 4 * DEC_];         // k-slab partials
__device__ float g_awe_p[B_ * 8 * ENC_];                   // awe numerator partials
__device__ float g_sum_p[B_ * 8];                          // exp-sum partials
__device__ unsigned g_bar_cnt[NBAR_];
__device__ unsigned g_bar_rel[NBAR_];

__device__ __forceinline__ float sigm(float x) { return 1.0f / (1.0f + __expf(-x)); }

// grid barrier (R8-proven primitives): atomicAdd arrival; CTA0 polls counter,
// publishes a separate release word; other CTAs poll the release word.
__device__ __forceinline__ void gridbar(int slot) {
    __syncthreads();
    if (threadIdx.x == 0) {
        __threadfence();                       // release
        atomicAdd(&g_bar_cnt[slot], 1u);
        if (blockIdx.x == 0) {
            unsigned c; long long guard = 0;
            do {
                asm volatile("ld.acquire.gpu.u32 %0, [%1];" : "=r"(c) : "l"(&g_bar_cnt[slot]));
                if (c >= GRID_) break;
                __nanosleep(32);
            } while (++guard < (1LL << 31));
            __threadfence();
            atomicExch(&g_bar_rel[slot], 1u);
        } else {
            unsigned r; long long guard = 0;
            do {
                asm volatile("ld.acquire.gpu.u32 %0, [%1];" : "=r"(r) : "l"(&g_bar_rel[slot]));
                if (r) break;
                __nanosleep(32);
            } while (++guard < (1LL << 31));
        }
        __threadfence();                       // acquire; fresh L1 for this CTA
    }
    __syncthreads();
}

// ---------------- prologue kernels ----------------
__global__ void k_enc_bf(const float* __restrict__ enc) {
    size_t i = (size_t)blockIdx.x * blockDim.x + threadIdx.x;
    const float4* in = (const float4*)enc;
    float4 v = in[i];
    __nv_bfloat162* out = (__nv_bfloat162*)g_enc_bf;
    out[i * 2]     = __floats2bfloat162_rn(v.x, v.y);
    out[i * 2 + 1] = __floats2bfloat162_rn(v.z, v.w);
}

__global__ void k_enc_att(const float* __restrict__ enc,
                          const float* __restrict__ W_enc,
                          const float* __restrict__ b_enc) {
    extern __shared__ float sm[];
    float* sWT = sm;                 // [128][257]
    float* sE  = sm + 128 * 257;     // [16][128]
    int tid = threadIdx.x;
    for (int idx = tid; idx < ATT_ * ENC_; idx += 256) {
        int a = idx >> 7, e = idx & 127;
        sWT[e * 257 + a] = W_enc[idx];
    }
    int row0 = blockIdx.x * 16;
    for (int idx = tid; idx < 16 * ENC_; idx += 256) {
        int r = idx >> 7, e = idx & 127;
        sE[r * ENC_ + e] = enc[(size_t)(row0 + r) * ENC_ + e];
    }
    __syncthreads();
    int a = tid;
    float bb = b_enc[a];
    float acc[16];
#pragma unroll
    for (int r = 0; r < 16; r++) acc[r] = bb;
    for (int e = 0; e < ENC_; e++) {
        float w = sWT[e * 257 + a];
#pragma unroll
        for (int r = 0; r < 16; r++) acc[r] = fmaf(sE[r * ENC_ + e], w, acc[r]);
    }
#pragma unroll
    for (int r = 0; r < 16; r++)
        g_enc_att_bf[(size_t)(row0 + r) * ATT_ + a] = __float2bfloat16(acc[r]);
}

__global__ void k_mean(const float* __restrict__ enc) {
    int b = blockIdx.x, tid = threadIdx.x;
    int g = tid >> 7, e = tid & 127;
    const float* base = enc + ((size_t)b * V_ + g * 512) * ENC_ + e;
    float s = 0.f;
#pragma unroll 8
    for (int v = 0; v < 512; v++) s += base[(size_t)v * ENC_];
    __shared__ float sp[4][128];
    sp[g][e] = s;
    __syncthreads();
    if (tid < 128)
        g_mean[b * ENC_ + tid] = (sp[0][tid] + sp[1][tid] + sp[2][tid] + sp[3][tid]) * (1.0f / V_);
}

__device__ __forceinline__ void attention_pre(int b, int tid, const float* sh,
                                              const float* __restrict__ W_dec,
                                              const float* __restrict__ b_dec,
                                              const float* __restrict__ W_beta,
                                              const float* __restrict__ b_beta) {
    const float4* h4 = (const float4*)sh;
    if (tid < ATT_) {
        float acc = b_dec[tid];
        const float4* w = (const float4*)(W_dec + tid * DEC_);
#pragma unroll 8
        for (int k = 0; k < DEC_ / 4; k++) {
            float4 a = w[k]; float4 h = h4[k];
            acc += a.x * h.x + a.y * h.y + a.z * h.z + a.w * h.w;
        }
        g_dec_att[b * ATT_ + tid] = acc;
    } else if (tid < ATT_ + ENC_) {
        int e = tid - ATT_;
        float acc = b_beta[e];
        const float4* w = (const float4*)(W_beta + e * DEC_);
#pragma unroll 8
        for (int k = 0; k < DEC_ / 4; k++) {
            float4 a = w[k]; float4 h = h4[k];
            acc += a.x * h.x + a.y * h.y + a.z * h.z + a.w * h.w;
        }
        g_gate[b * ENC_ + e] = sigm(acc);
    }
}

__global__ void k_init(const float* __restrict__ Wh, const float* __restrict__ bh,
                       const float* __restrict__ Wc, const float* __restrict__ bc,
                       const float* __restrict__ W_dec, const float* __restrict__ b_dec,
                       const float* __restrict__ W_beta, const float* __restrict__ b_beta,
                       const int* __restrict__ caps, const float* __restrict__ emb_W) {
    int b = blockIdx.x, tid = threadIdx.x;
    __shared__ float smn[ENC_];
    __shared__ float sh[DEC_];
    if (tid < ENC_) smn[tid] = g_mean[b * ENC_ + tid];
    __syncthreads();
    {
        int d = tid;
        float ah = bh[d], ac = bc[d];
        const float4* wrh = (const float4*)(Wh + d * ENC_);
        const float4* wrc = (const float4*)(Wc + d * ENC_);
        const float4* mv  = (const float4*)smn;
#pragma unroll 8
        for (int k = 0; k < ENC_ / 4; k++) {
            float4 m4 = mv[k]; float4 h4 = wrh[k]; float4 c4 = wrc[k];
            ah += m4.x * h4.x + m4.y * h4.y + m4.z * h4.z + m4.w * h4.w;
            ac += m4.x * c4.x + m4.y * c4.y + m4.z * c4.z + m4.w * c4.w;
        }
        g_h[b * DEC_ + d] = ah;
        g_c[b * DEC_ + d] = ac;
        sh[d] = ah;
    }
    if (tid < 256) {
        int cap = caps[b * T_];
        g_x[b * XDIM_ + tid] = emb_W[cap * EMB_ + tid];
    }
    __syncthreads();
    attention_pre(b, tid, sh, W_dec, b_dec, W_beta, b_beta);
}

// ---------------- persistent loop kernel ----------------
__global__ void __launch_bounds__(NTHR_, 1)
k_loop(const int* __restrict__ lens, const int* __restrict__ caps,
       const float* __restrict__ emb_W,
       const float* __restrict__ w_full, const float* __restrict__ b_full,
       const float* __restrict__ W_ih, const float* __restrict__ W_hh,
       const float* __restrict__ b_ih, const float* __restrict__ b_hh,
       const float* __restrict__ W_dec, const float* __restrict__ b_dec,
       const float* __restrict__ W_beta, const float* __restrict__ b_beta,
       const float* __restrict__ W_final, const float* __restrict__ b_final,
       float* __restrict__ out_pred, float* __restrict__ out_alpha)
{
    extern __shared__ float sm[];
    const int cta = blockIdx.x, tid = threadIdx.x;
    const int warp = tid >> 5, lane = tid & 31;
    int bs = 0;

    for (int t = 0; t < T_; t++) {
        // ===== Phase A': exp(scores) + exp-sum partials + awe numerator partials =====
        // tasks = 64 b x 8 chunks(256 v)
        {
            float* sda   = sm;           // [256]
            float* sw    = sm + 256;     // [256]
            float* s_exp = sm + 512;     // [256]
            float* swsum = sm + 768;     // [32]
            float* part  = sm + 800;     // [8][128]
            float bf = b_full[0];
            for (int task = cta; task < 512; task += GRID_) {
                int b = task >> 3, c = task & 7;
                int v0 = c * 256;
                __syncthreads();
                if (tid < 256) sda[tid] = g_dec_att[b * ATT_ + tid];
                else if (tid < 512) sw[tid - 256] = w_full[tid - 256];
                __syncthreads();
                float esum = 0.f;
#pragma unroll
                for (int r = 0; r < 8; r++) {
                    int v = v0 + warp * 8 + r;
                    const __nv_bfloat162* row =
                        (const __nv_bfloat162*)(g_enc_att_bf + (size_t)(b * V_ + v) * ATT_);
                    float acc = 0.f;
#pragma unroll
                    for (int k = 0; k < 4; k++) {
                        int a2 = lane + k * 32;
                        float2 e2 = __bfloat1622float2(row[a2]);
                        int a = a2 * 2;
                        acc += fmaxf(e2.x + sda[a], 0.f) * sw[a]
                             + fmaxf(e2.y + sda[a + 1], 0.f) * sw[a + 1];
                    }
#pragma unroll
                    for (int o = 16; o; o >>= 1) acc += __shfl_xor_sync(0xFFFFFFFFu, acc, o);
                    if (lane == 0) {
                        float e = __expf(acc + bf);        // scores tiny: no max needed
                        g_scores[b * V_ + v] = e;
                        s_exp[warp * 8 + r] = e;
                        esum += e;
                    }
                }
                if (lane == 0) swsum[warp] = esum;
                __syncthreads();
                if (tid < 32) {
                    float s2 = swsum[tid];
#pragma unroll
                    for (int o = 16; o; o >>= 1) s2 += __shfl_xor_sync(0xFFFFFFFFu, s2, o);
                    if (tid == 0) g_sum_p[b * 8 + c] = s2;
                }
                // awe numerator partial over this chunk's 256 voxels
                int sub = tid >> 7, e = tid & 127;
                const __nv_bfloat16* base =
                    g_enc_bf + ((size_t)b * V_ + v0 + sub * 32) * ENC_ + e;
                const float* ap = s_exp + sub * 32;
                float s = 0.f;
#pragma unroll 8
                for (int v = 0; v < 32; v++) s += ap[v] * __bfloat162float(base[(size_t)v * ENC_]);
                part[sub * 128 + e] = s;
                __syncthreads();
                if (tid < 128) {
                    float tot = 0.f;
#pragma unroll
                    for (int k = 0; k < 8; k++) tot += part[k * 128 + tid];
                    g_awe_p[(b * 8 + c) * ENC_ + tid] = tot;
                }
            }
        }
        gridbar(bs++);

        // ===== Phase C': gates GEMM (awe normalized inline) + alpha write =====
        // tasks = 16 j-tiles(128 j) x 8 k-slabs(112 k); 128 tasks
        {
            float* sXT  = sm;                           // [112][68]
            float* sW   = sm + KSL_ * 68;               // [128][113]
            float* sinv = sm + KSL_ * 68 + 128 * 113;   // [64]
            int jj = tid >> 3, b8 = tid & 7;
            for (int task = cta; task < 128; task += GRID_) {
                int jt = task >> 3, ks = task & 7;
                int j0 = jt * 128, k0 = ks * KSL_;
                __syncthreads();
                if (tid < 64) {
                    float s = 0.f;
#pragma unroll
                    for (int c = 0; c < 8; c++) s += g_sum_p[tid * 8 + c];
                    sinv[tid] = 1.0f / s;
                }
                // W slab: 128 j x 112 k
#pragma unroll
                for (int r = 0; r < 14; r++) {
                    int idx = tid + r * 1024;
                    int j2 = idx / KSL_, kk = idx - j2 * KSL_;
                    int gk = k0 + kk;
                    int j = j0 + j2;
                    float w = (gk < 384) ? W_ih[j * 384 + gk] : W_hh[j * DEC_ + gk - 384];
                    sW[j2 * 113 + kk] = w;
                }
                __syncthreads();
                // X^T slab: 64 b x 112 k (awe built inline, normalized & gated)
#pragma unroll
                for (int r = 0; r < 7; r++) {
                    int idx = tid + r * 1024;
                    int b = idx / KSL_, k = idx - b * KSL_;
                    int gk = k0 + k;
                    float v;
                    if (gk < 256) {
                        v = g_x[b * XDIM_ + gk];
                    } else if (gk < 384) {
                        int e = gk - 256;
                        float s = 0.f;
#pragma unroll
                        for (int c = 0; c < 8; c++) s += g_awe_p[(b * 8 + c) * ENC_ + e];
                        v = s * sinv[b] * g_gate[b * ENC_ + e];
                    } else {
                        v = g_h[b * DEC_ + gk - 384];
                    }
                    sXT[k * 68 + b] = v;
                }
                __syncthreads();
                float acc[8] = {0.f, 0.f, 0.f, 0.f, 0.f, 0.f, 0.f, 0.f};
                const float* wrow = sW + jj * 113;
#pragma unroll 4
                for (int kk = 0; kk < KSL_; kk++) {
                    float w = wrow[kk];
                    const float4* x4 = (const float4*)(sXT + kk * 68 + b8 * 8);
                    float4 xa = x4[0], xb = x4[1];
                    acc[0] = fmaf(xa.x, w, acc[0]);
                    acc[1] = fmaf(xa.y, w, acc[1]);
                    acc[2] = fmaf(xa.z, w, acc[2]);
                    acc[3] = fmaf(xa.w, w, acc[3]);
                    acc[4] = fmaf(xb.x, w, acc[4]);
                    acc[5] = fmaf(xb.y, w, acc[5]);
                    acc[6] = fmaf(xb.z, w, acc[6]);
                    acc[7] = fmaf(xb.w, w, acc[7]);
                }
                int j = j0 + jj;
#pragma unroll
                for (int i = 0; i < 8; i++)
                    g_gates_p[ks][(b8 * 8 + i) * (4 * DEC_) + j] = acc[i];
                // alpha write: task -> (b = task>>1, half = task&1)
                {
                    int ab = task >> 1, half = task & 1;
                    float inv = sinv[ab];
                    bool msk = t < lens[ab];
                    float al = g_scores[ab * V_ + half * 1024 + tid] * inv;
                    out_alpha[(size_t)(ab * T_ + t) * V_ + half * 1024 + tid] = msk ? al : 0.f;
                }
            }
        }
        gridbar(bs++);

        // ===== Phase D: LSTM cell + emb prefetch (64 CTAs) =====
        if (cta < B_) {
            int b = cta;
            bool msk = t < lens[b];
            if (tid < DEC_) {
                int d = tid;
                int base = b * 4 * DEC_;
                float gi = b_ih[d] + b_hh[d];
                float gf = b_ih[DEC_ + d] + b_hh[DEC_ + d];
                float gg = b_ih[2 * DEC_ + d] + b_hh[2 * DEC_ + d];
                float go = b_ih[3 * DEC_ + d] + b_hh[3 * DEC_ + d];
#pragma unroll
                for (int s = 0; s < NSLAB_; s++) {
                    gi += g_gates_p[s][base + d];
                    gf += g_gates_p[s][base + DEC_ + d];
                    gg += g_gates_p[s][base + 2 * DEC_ + d];
                    go += g_gates_p[s][base + 3 * DEC_ + d];
                }
                float ig = sigm(gi), fg = sigm(gf), og = sigm(go);
                float gt = tanhf(gg);
                float c_old = g_c[b * DEC_ + d];
                float cn = fg * c_old + ig * gt;
                float hn = og * tanhf(cn);
                float h_old = g_h[b * DEC_ + d];
                g_h[b * DEC_ + d] = msk ? hn : h_old;
                g_c[b * DEC_ + d] = msk ? cn : c_old;
                g_hn[b * DEC_ + d] = hn;
            } else if (tid < DEC_ + EMB_) {
                if (t + 1 < T_) {
                    int e = tid - DEC_;
                    int cap = caps[b * T_ + t + 1];
                    g_x[b * XDIM_ + e] = emb_W[cap * EMB_ + e];
                }
            }
        }
        gridbar(bs++);

        // ===== Phase E: dec_att/gate/pred GEMV on raw h_new, predicated stores =====
        // tasks = 26 x 16 rows; thread = (b 64, ks 4, rq 4); W read once
        {
            float* red = sm;   // [16][4][64]
            for (int task = cta; task < 26; task += GRID_) {
                int jbase = task * 16;
                int b = tid & 63, ks = (tid >> 6) & 3, rq = tid >> 8;
                const float4* h4 = (const float4*)(g_hn + b * DEC_ + ks * 128);
                const float4* wr[4];
#pragma unroll
                for (int rl = 0; rl < 4; rl++) {
                    int j = jbase + rq * 4 + rl;
                    int jc = (j < NROW_) ? j : (NROW_ - 1);
                    const float* Wrow;
                    if (jc < 256)      Wrow = W_dec   + jc * DEC_;
                    else if (jc < 384) Wrow = W_beta  + (jc - 256) * DEC_;
                    else               Wrow = W_final + (jc - 384) * DEC_;
                    wr[rl] = (const float4*)(Wrow + ks * 128);
                }
                float acc[4] = {0.f, 0.f, 0.f, 0.f};
#pragma unroll
                for (int sub = 0; sub < 4; sub++) {
                    float4 h[8];
#pragma unroll
                    for (int i = 0; i < 8; i++) h[i] = h4[sub * 8 + i];
#pragma unroll
                    for (int rl = 0; rl < 4; rl++) {
#pragma unroll
                        for (int i = 0; i < 8; i++) {
                            float4 w = wr[rl][sub * 8 + i];
                            acc[rl] += w.x * h[i].x + w.y * h[i].y
                                     + w.z * h[i].z + w.w * h[i].w;
                        }
                    }
                }
#pragma unroll
                for (int rl = 0; rl < 4; rl++)
                    red[(rq * 4 + rl) * 256 + ks * 64 + b] = acc[rl];
                __syncthreads();
                {
                    int jl = tid >> 6, b2 = tid & 63;
                    int j = jbase + jl;
                    float s = red[jl * 256 + b2]       + red[jl * 256 + 64 + b2]
                            + red[jl * 256 + 128 + b2] + red[jl * 256 + 192 + b2];
                    if (j < NROW_) {
                        bool msk = t < lens[b2];
                        if (j < 256) {
                            if (msk) g_dec_att[b2 * ATT_ + j] = s + b_dec[j];
                        } else if (j < 384) {
                            if (msk) g_gate[b2 * ENC_ + (j - 256)] = sigm(s + b_beta[j - 256]);
                        } else {
                            out_pred[(size_t)(b2 * T_ + t) * VOC_ + (j - 384)] =
                                msk ? (s + b_final[j - 384]) : 0.f;
                        }
                    }
                }
                __syncthreads();
            }
        }
        gridbar(bs++);
    }
}

__global__ void k_reset(const int* __restrict__ lens, float* __restrict__ out_lens) {
    int i = threadIdx.x;
    if (i < NBAR_) { g_bar_cnt[i] = 0; g_bar_rel[i] = 0; }
    if (i < B_) out_lens[i] = (float)lens[i];
}

// ---------------- launch ----------------
extern "C" void kernel_launch(void* const* d_in, const int* in_sizes, int n_in,
                              void* d_out, int out_size) {
    const float* enc      = (const float*)d_in[0];
    const int*   caps     = (const int*)  d_in[1];
    const int*   lens     = (const int*)  d_in[2];
    const float* emb_W    = (const float*)d_in[3];
    const float* W_enc    = (const float*)d_in[4];
    const float* b_enc    = (const float*)d_in[5];
    const float* W_dec    = (const float*)d_in[6];
    const float* b_dec    = (const float*)d_in[7];
    const float* w_full   = (const float*)d_in[8];
    const float* b_full   = (const float*)d_in[9];
    const float* W_ih     = (const float*)d_in[10];
    const float* b_ih     = (const float*)d_in[11];
    const float* W_hh     = (const float*)d_in[12];
    const float* b_hh     = (const float*)d_in[13];
    const float* W_init_h = (const float*)d_in[14];
    const float* b_init_h = (const float*)d_in[15];
    const float* W_init_c = (const float*)d_in[16];
    const float* b_init_c = (const float*)d_in[17];
    const float* W_beta   = (const float*)d_in[18];
    const float* b_beta   = (const float*)d_in[19];
    const float* W_final  = (const float*)d_in[20];
    const float* b_final  = (const float*)d_in[21];

    float* out       = (float*)d_out;
    float* out_pred  = out;
    float* out_alpha = out + (size_t)B_ * T_ * VOC_;
    float* out_lens  = out_alpha + (size_t)B_ * T_ * V_;

    const int SMEM_EA   = (128 * 257 + 16 * 128) * 4;                // 139776 B
    const int SMEM_LOOP = (KSL_ * 68 + 128 * 113 + 64) * 4;          // 88576 B
    static bool attr_done = false;
    if (!attr_done) {
        cudaFuncSetAttribute(k_enc_att, cudaFuncAttributeMaxDynamicSharedMemorySize, SMEM_EA);
        cudaFuncSetAttribute(k_loop, cudaFuncAttributeMaxDynamicSharedMemorySize, SMEM_LOOP);
        attr_done = true;
    }

    k_enc_bf<<<(B_ * V_ * ENC_) / 4 / 256, 256>>>(enc);
    k_enc_att<<<(B_ * V_) / 16, 256, SMEM_EA>>>(enc, W_enc, b_enc);
    k_mean<<<B_, 512>>>(enc);
    k_init<<<B_, 512>>>(W_init_h, b_init_h, W_init_c, b_init_c,
                        W_dec, b_dec, W_beta, b_beta, caps, emb_W);
    k_loop<<<GRID_, NTHR_, SMEM_LOOP>>>(lens, caps, emb_W, w_full, b_full,
                                        W_ih, W_hh, b_ih, b_hh,
                                        W_dec, b_dec, W_beta, b_beta,
                                        W_final, b_final, out_pred, out_alpha);
    k_reset<<<1, 512>>>(lens, out_lens);
}

// round 12
// speedup vs baseline: 1.1087x; 1.1087x over previous
#include <cuda_runtime.h>
#include <cuda_bf16.h>
#include <cstdint>

#define B_    64
#define V_    2048
#define ENC_  128
#define T_    100
#define EMB_  256
#define DEC_  512
#define ATT_  256
#define VOC_  29
#define XDIM_ 896
#define NROW_ 413   // 256 dec_att + 128 gate + 29 pred

#define GRID_ 148
#define NTHR_ 1024
#define NBAR_ 400    // 4 barriers * 100 steps

// ---------------- scratch ----------------
__device__ __nv_bfloat16 g_enc_att_bf[(size_t)B_ * V_ * ATT_];   // 67 MB
__device__ __nv_bfloat16 g_enc_bf[(size_t)B_ * V_ * ENC_];       // 33.5 MB
__device__ float g_mean[B_ * ENC_];
__device__ float g_h[B_ * DEC_];
__device__ float g_hn[B_ * DEC_];
__device__ float g_c[B_ * DEC_];
__device__ float g_dec_att[B_ * ATT_];
__device__ float g_gate[B_ * ENC_];
__device__ float g_scores[B_ * V_];                        // holds exp(score)
__device__ float g_x[B_ * XDIM_];                          // [emb | (unused) | h]
__device__ float g_gates_p[2][B_ * 4 * DEC_];              // slab partials
__device__ float g_awe_p[B_ * 8 * ENC_];                   // awe numerator partials
__device__ float g_sum_p[B_ * 8];                          // exp-sum partials
__device__ unsigned g_bar_slots[NBAR_];                    // zeroed by k_reset

__device__ __forceinline__ float sigm(float x) { return 1.0f / (1.0f + __expf(-x)); }

// v1 grid barrier (the 9820-champion form): atomicAdd one slot, all CTAs poll it
__device__ __forceinline__ void gridbar(int slot) {
    __syncthreads();
    if (threadIdx.x == 0) {
        __threadfence();                         // release
        unsigned* p = &g_bar_slots[slot];
        unsigned v = atomicAdd(p, 1u) + 1u;
        if (v < GRID_) {
            unsigned cur; long long guard = 0;
            do {
                asm volatile("ld.acquire.gpu.u32 %0, [%1];" : "=r"(cur) : "l"(p));
                if (cur >= GRID_) break;
                __nanosleep(32);
            } while (++guard < (1LL << 31));
        }
        __threadfence();                         // acquire; fresh L1
    }
    __syncthreads();
}

// ---------------- prologue kernels ----------------
__global__ void k_enc_bf(const float* __restrict__ enc) {
    size_t i = (size_t)blockIdx.x * blockDim.x + threadIdx.x;
    const float4* in = (const float4*)enc;
    float4 v = in[i];
    __nv_bfloat162* out = (__nv_bfloat162*)g_enc_bf;
    out[i * 2]     = __floats2bfloat162_rn(v.x, v.y);
    out[i * 2 + 1] = __floats2bfloat162_rn(v.z, v.w);
}

__global__ void k_enc_att(const float* __restrict__ enc,
                          const float* __restrict__ W_enc,
                          const float* __restrict__ b_enc) {
    extern __shared__ float sm[];
    float* sWT = sm;                 // [128][257]
    float* sE  = sm + 128 * 257;     // [16][128]
    int tid = threadIdx.x;
    for (int idx = tid; idx < ATT_ * ENC_; idx += 256) {
        int a = idx >> 7, e = idx & 127;
        sWT[e * 257 + a] = W_enc[idx];
    }
    int row0 = blockIdx.x * 16;
    for (int idx = tid; idx < 16 * ENC_; idx += 256) {
        int r = idx >> 7, e = idx & 127;
        sE[r * ENC_ + e] = enc[(size_t)(row0 + r) * ENC_ + e];
    }
    __syncthreads();
    int a = tid;
    float bb = b_enc[a];
    float acc[16];
#pragma unroll
    for (int r = 0; r < 16; r++) acc[r] = bb;
    for (int e = 0; e < ENC_; e++) {
        float w = sWT[e * 257 + a];
#pragma unroll
        for (int r = 0; r < 16; r++) acc[r] = fmaf(sE[r * ENC_ + e], w, acc[r]);
    }
#pragma unroll
    for (int r = 0; r < 16; r++)
        g_enc_att_bf[(size_t)(row0 + r) * ATT_ + a] = __float2bfloat16(acc[r]);
}

__global__ void k_mean(const float* __restrict__ enc) {
    int b = blockIdx.x, tid = threadIdx.x;
    int g = tid >> 7, e = tid & 127;
    const float* base = enc + ((size_t)b * V_ + g * 512) * ENC_ + e;
    float s = 0.f;
#pragma unroll 8
    for (int v = 0; v < 512; v++) s += base[(size_t)v * ENC_];
    __shared__ float sp[4][128];
    sp[g][e] = s;
    __syncthreads();
    if (tid < 128)
        g_mean[b * ENC_ + tid] = (sp[0][tid] + sp[1][tid] + sp[2][tid] + sp[3][tid]) * (1.0f / V_);
}

__device__ __forceinline__ void attention_pre(int b, int tid, const float* sh,
                                              const float* __restrict__ W_dec,
                                              const float* __restrict__ b_dec,
                                              const float* __restrict__ W_beta,
                                              const float* __restrict__ b_beta) {
    const float4* h4 = (const float4*)sh;
    if (tid < ATT_) {
        float acc = b_dec[tid];
        const float4* w = (const float4*)(W_dec + tid * DEC_);
#pragma unroll 8
        for (int k = 0; k < DEC_ / 4; k++) {
            float4 a = w[k]; float4 h = h4[k];
            acc += a.x * h.x + a.y * h.y + a.z * h.z + a.w * h.w;
        }
        g_dec_att[b * ATT_ + tid] = acc;
    } else if (tid < ATT_ + ENC_) {
        int e = tid - ATT_;
        float acc = b_beta[e];
        const float4* w = (const float4*)(W_beta + e * DEC_);
#pragma unroll 8
        for (int k = 0; k < DEC_ / 4; k++) {
            float4 a = w[k]; float4 h = h4[k];
            acc += a.x * h.x + a.y * h.y + a.z * h.z + a.w * h.w;
        }
        g_gate[b * ENC_ + e] = sigm(acc);
    }
}

__global__ void k_init(const float* __restrict__ Wh, const float* __restrict__ bh,
                       const float* __restrict__ Wc, const float* __restrict__ bc,
                       const float* __restrict__ W_dec, const float* __restrict__ b_dec,
                       const float* __restrict__ W_beta, const float* __restrict__ b_beta,
                       const int* __restrict__ caps, const float* __restrict__ emb_W) {
    int b = blockIdx.x, tid = threadIdx.x;
    __shared__ float smn[ENC_];
    __shared__ float sh[DEC_];
    if (tid < ENC_) smn[tid] = g_mean[b * ENC_ + tid];
    __syncthreads();
    {
        int d = tid;
        float ah = bh[d], ac = bc[d];
        const float4* wrh = (const float4*)(Wh + d * ENC_);
        const float4* wrc = (const float4*)(Wc + d * ENC_);
        const float4* mv  = (const float4*)smn;
#pragma unroll 8
        for (int k = 0; k < ENC_ / 4; k++) {
            float4 m4 = mv[k]; float4 h4 = wrh[k]; float4 c4 = wrc[k];
            ah += m4.x * h4.x + m4.y * h4.y + m4.z * h4.z + m4.w * h4.w;
            ac += m4.x * c4.x + m4.y * c4.y + m4.z * c4.z + m4.w * c4.w;
        }
        g_h[b * DEC_ + d] = ah;
        g_c[b * DEC_ + d] = ac;
        g_x[b * XDIM_ + EMB_ + ENC_ + d] = ah;
        sh[d] = ah;
    }
    if (tid < 256) {
        int cap = caps[b * T_];
        g_x[b * XDIM_ + tid] = emb_W[cap * EMB_ + tid];
    }
    __syncthreads();
    attention_pre(b, tid, sh, W_dec, b_dec, W_beta, b_beta);
}

// ---------------- persistent loop kernel ----------------
__global__ void __launch_bounds__(NTHR_, 1)
k_loop(const int* __restrict__ lens, const int* __restrict__ caps,
       const float* __restrict__ emb_W,
       const float* __restrict__ w_full, const float* __restrict__ b_full,
       const float* __restrict__ W_ih, const float* __restrict__ W_hh,
       const float* __restrict__ b_ih, const float* __restrict__ b_hh,
       const float* __restrict__ W_dec, const float* __restrict__ b_dec,
       const float* __restrict__ W_beta, const float* __restrict__ b_beta,
       const float* __restrict__ W_final, const float* __restrict__ b_final,
       float* __restrict__ out_pred, float* __restrict__ out_alpha)
{
    extern __shared__ float sm[];
    const int cta = blockIdx.x, tid = threadIdx.x;
    const int warp = tid >> 5, lane = tid & 31;
    int bs = 0;

    for (int t = 0; t < T_; t++) {
        // ===== Phase A: exp(scores) + exp-sum partials + awe numerator partials =====
        // tasks = 64 b x 8 chunks(256 v)
        {
            float* sda   = sm;           // [256]
            float* sw    = sm + 256;     // [256]
            float* s_exp = sm + 512;     // [256]
            float* swsum = sm + 768;     // [32]
            float* part  = sm + 800;     // [8][128]
            float bf = b_full[0];
            for (int task = cta; task < 512; task += GRID_) {
                int b = task >> 3, c = task & 7;
                int v0 = c * 256;
                __syncthreads();
                if (tid < 256) sda[tid] = g_dec_att[b * ATT_ + tid];
                else if (tid < 512) sw[tid - 256] = w_full[tid - 256];
                __syncthreads();
                float esum = 0.f;
#pragma unroll
                for (int r = 0; r < 8; r++) {
                    int v = v0 + warp * 8 + r;
                    const __nv_bfloat162* row =
                        (const __nv_bfloat162*)(g_enc_att_bf + (size_t)(b * V_ + v) * ATT_);
                    float acc = 0.f;
#pragma unroll
                    for (int k = 0; k < 4; k++) {
                        int a2 = lane + k * 32;
                        float2 e2 = __bfloat1622float2(row[a2]);
                        int a = a2 * 2;
                        acc += fmaxf(e2.x + sda[a], 0.f) * sw[a]
                             + fmaxf(e2.y + sda[a + 1], 0.f) * sw[a + 1];
                    }
#pragma unroll
                    for (int o = 16; o; o >>= 1) acc += __shfl_xor_sync(0xFFFFFFFFu, acc, o);
                    if (lane == 0) {
                        float e = __expf(acc + bf);   // scores bounded: no max needed
                        g_scores[b * V_ + v] = e;
                        s_exp[warp * 8 + r] = e;
                        esum += e;
                    }
                }
                if (lane == 0) swsum[warp] = esum;
                __syncthreads();
                if (tid < 32) {
                    float s2 = swsum[tid];
#pragma unroll
                    for (int o = 16; o; o >>= 1) s2 += __shfl_xor_sync(0xFFFFFFFFu, s2, o);
                    if (tid == 0) g_sum_p[b * 8 + c] = s2;
                }
                // awe numerator partial over this chunk's 256 voxels
                int sub = tid >> 7, e = tid & 127;
                const __nv_bfloat16* base =
                    g_enc_bf + ((size_t)b * V_ + v0 + sub * 32) * ENC_ + e;
                const float* ap = s_exp + sub * 32;
                float s = 0.f;
#pragma unroll 8
                for (int v = 0; v < 32; v++) s += ap[v] * __bfloat162float(base[(size_t)v * ENC_]);
                part[sub * 128 + e] = s;
                __syncthreads();
                if (tid < 128) {
                    float tot = 0.f;
#pragma unroll
                    for (int k = 0; k < 8; k++) tot += part[k * 128 + tid];
                    g_awe_p[(b * 8 + c) * ENC_ + tid] = tot;
                }
            }
        }
        gridbar(bs++);

        // ===== Phase C: gates GEMM (R6-proven layout) + awe synth + alpha write =====
        // tasks = 2 slabs x 128 j-tiles(16 j)
        {
            float* sX   = sm;                    // [64][132]
            float* sW   = sm + 64 * 132;         // [16][133]
            float* red  = sW + 16 * 133;         // [4096]
            float* sinv = red + 4096;            // [64]
            int jj = tid & 15, bq = (tid >> 4) & 15, ks = tid >> 8;
            for (int task = cta; task < 256; task += GRID_) {
                int slab = task >> 7;
                int j0 = (task & 127) * 16;
                const float* src = slab ? W_hh : W_ih;
                int ld  = slab ? DEC_ : 384;
                int kx0 = slab ? 384 : 0;
                int nch = slab ? 4 : 3;
                __syncthreads();
                if (tid < 64) {
                    float s = 0.f;
#pragma unroll
                    for (int c = 0; c < 8; c++) s += g_sum_p[tid * 8 + c];
                    sinv[tid] = 1.0f / s;
                }
                __syncthreads();
                if (task < 128) {   // alpha write: b = task>>1, half = task&1
                    int ab = task >> 1, half = task & 1;
                    bool msk = t < lens[ab];
                    float al = g_scores[ab * V_ + half * 1024 + tid] * sinv[ab];
                    out_alpha[(size_t)(ab * T_ + t) * V_ + half * 1024 + tid] = msk ? al : 0.f;
                }
                float acc[4] = {0.f, 0.f, 0.f, 0.f};
                for (int kc = 0; kc < nch; kc++) {
                    int k0 = kc * 128;
                    __syncthreads();
#pragma unroll
                    for (int r = 0; r < 8; r++) {
                        int idx = tid + r * 1024;
                        int bb = idx >> 7, kk = idx & 127;
                        int gk = kx0 + k0 + kk;
                        float v;
                        if (gk < 256 || gk >= 384) {
                            v = g_x[bb * XDIM_ + gk];
                        } else {
                            int e = gk - 256;
                            float s = 0.f;
#pragma unroll
                            for (int c = 0; c < 8; c++) s += g_awe_p[(bb * 8 + c) * ENC_ + e];
                            v = s * sinv[bb] * g_gate[bb * ENC_ + e];
                        }
                        sX[bb * 132 + kk] = v;
                    }
#pragma unroll
                    for (int r = 0; r < 2; r++) {
                        int e2 = tid + r * 1024;
                        int j2 = e2 >> 7, kk = e2 & 127;
                        sW[j2 * 133 + kk] = src[(j0 + j2) * ld + k0 + kk];
                    }
                    __syncthreads();
                    const float* wrow = sW + jj * 133 + ks * 32;
#pragma unroll
                    for (int kk = 0; kk < 32; kk++) {
                        float w = wrow[kk];
#pragma unroll
                        for (int i = 0; i < 4; i++)
                            acc[i] = fmaf(sX[(bq * 4 + i) * 132 + ks * 32 + kk], w, acc[i]);
                    }
                }
                __syncthreads();
#pragma unroll
                for (int i = 0; i < 4; i++)
                    red[(ks * 256 + bq * 16 + jj) * 4 + i] = acc[i];
                __syncthreads();
                {
                    int jr = tid & 15, br = (tid >> 4) & 15, ir = tid >> 8;
                    float s = red[(0 * 256 + br * 16 + jr) * 4 + ir]
                            + red[(1 * 256 + br * 16 + jr) * 4 + ir]
                            + red[(2 * 256 + br * 16 + jr) * 4 + ir]
                            + red[(3 * 256 + br * 16 + jr) * 4 + ir];
                    int b = br * 4 + ir;
                    g_gates_p[slab][b * (4 * DEC_) + j0 + jr] = s;
                }
            }
        }
        gridbar(bs++);

        // ===== Phase D: LSTM cell (elementwise) + emb prefetch (64 CTAs) =====
        if (cta < B_) {
            int b = cta;
            bool msk = t < lens[b];
            if (tid < DEC_) {
                int d = tid;
                int base = b * 4 * DEC_;
                float gi = g_gates_p[0][base + d]            + g_gates_p[1][base + d]
                         + b_ih[d]            + b_hh[d];
                float gf = g_gates_p[0][base + DEC_ + d]     + g_gates_p[1][base + DEC_ + d]
                         + b_ih[DEC_ + d]     + b_hh[DEC_ + d];
                float gg = g_gates_p[0][base + 2 * DEC_ + d] + g_gates_p[1][base + 2 * DEC_ + d]
                         + b_ih[2 * DEC_ + d] + b_hh[2 * DEC_ + d];
                float go = g_gates_p[0][base + 3 * DEC_ + d] + g_gates_p[1][base + 3 * DEC_ + d]
                         + b_ih[3 * DEC_ + d] + b_hh[3 * DEC_ + d];
                float ig = sigm(gi), fg = sigm(gf), og = sigm(go);
                float gt = tanhf(gg);
                float c_old = g_c[b * DEC_ + d];
                float cn = fg * c_old + ig * gt;
                float hn = og * tanhf(cn);
                float h_old = g_h[b * DEC_ + d];
                float h2 = msk ? hn : h_old;
                g_h[b * DEC_ + d] = h2;
                g_c[b * DEC_ + d] = msk ? cn : c_old;
                g_hn[b * DEC_ + d] = hn;
                g_x[b * XDIM_ + EMB_ + ENC_ + d] = h2;
            } else if (tid < DEC_ + EMB_) {
                if (t + 1 < T_) {
                    int e = tid - DEC_;
                    int cap = caps[b * T_ + t + 1];
                    g_x[b * XDIM_ + e] = emb_W[cap * EMB_ + e];
                }
            }
        }
        gridbar(bs++);

        // ===== Phase E: dec_att/gate/pred GEMV (R6-proven 104 tasks x 4 rows) =====
        {
            float* red = sm;                 // [4 rr][4 ks][64 b]
            int rr = tid >> 8, ks = (tid >> 6) & 3, b = tid & 63;
            for (int task = cta; task < 104; task += GRID_) {
                int r0 = task * 4;
                int j = r0 + rr;
                float acc = 0.f;
                __syncthreads();
                if (j < NROW_) {
                    const float* W;
                    if (j < 256)      W = W_dec   + j * DEC_;
                    else if (j < 384) W = W_beta  + (j - 256) * DEC_;
                    else              W = W_final + (j - 384) * DEC_;
                    const float* H = (j < 384) ? g_h : g_hn;
                    const float4* w4 = (const float4*)(W) + ks * 32;
                    const float4* h4 = (const float4*)(H + b * DEC_) + ks * 32;
#pragma unroll 8
                    for (int k = 0; k < 32; k++) {
                        float4 w = w4[k]; float4 x = h4[k];
                        acc += w.x * x.x + w.y * x.y + w.z * x.z + w.w * x.w;
                    }
                }
                red[(rr * 4 + ks) * 64 + b] = acc;
                __syncthreads();
                if (tid < 256) {
                    int rr2 = tid >> 6, b2 = tid & 63;
                    int j2 = r0 + rr2;
                    if (j2 < NROW_) {
                        float s = red[(rr2 * 4 + 0) * 64 + b2] + red[(rr2 * 4 + 1) * 64 + b2]
                                + red[(rr2 * 4 + 2) * 64 + b2] + red[(rr2 * 4 + 3) * 64 + b2];
                        if (j2 < 256)
                            g_dec_att[b2 * ATT_ + j2] = s + b_dec[j2];
                        else if (j2 < 384)
                            g_gate[b2 * ENC_ + (j2 - 256)] = sigm(s + b_beta[j2 - 256]);
                        else {
                            bool msk = t < lens[b2];
                            out_pred[(size_t)(b2 * T_ + t) * VOC_ + (j2 - 384)] =
                                msk ? (s + b_final[j2 - 384]) : 0.f;
                        }
                    }
                }
            }
        }
        gridbar(bs++);
    }
}

__global__ void k_reset(const int* __restrict__ lens, float* __restrict__ out_lens) {
    int i = threadIdx.x;
    if (i < NBAR_) g_bar_slots[i] = 0;
    if (i < B_) out_lens[i] = (float)lens[i];
}

// ---------------- launch ----------------
extern "C" void kernel_launch(void* const* d_in, const int* in_sizes, int n_in,
                              void* d_out, int out_size) {
    const float* enc      = (const float*)d_in[0];
    const int*   caps     = (const int*)  d_in[1];
    const int*   lens     = (const int*)  d_in[2];
    const float* emb_W    = (const float*)d_in[3];
    const float* W_enc    = (const float*)d_in[4];
    const float* b_enc    = (const float*)d_in[5];
    const float* W_dec    = (const float*)d_in[6];
    const float* b_dec    = (const float*)d_in[7];
    const float* w_full   = (const float*)d_in[8];
    const float* b_full   = (const float*)d_in[9];
    const float* W_ih     = (const float*)d_in[10];
    const float* b_ih     = (const float*)d_in[11];
    const float* W_hh     = (const float*)d_in[12];
    const float* b_hh     = (const float*)d_in[13];
    const float* W_init_h = (const float*)d_in[14];
    const float* b_init_h = (const float*)d_in[15];
    const float* W_init_c = (const float*)d_in[16];
    const float* b_init_c = (const float*)d_in[17];
    const float* W_beta   = (const float*)d_in[18];
    const float* b_beta   = (const float*)d_in[19];
    const float* W_final  = (const float*)d_in[20];
    const float* b_final  = (const float*)d_in[21];

    float* out       = (float*)d_out;
    float* out_pred  = out;
    float* out_alpha = out + (size_t)B_ * T_ * VOC_;
    float* out_lens  = out_alpha + (size_t)B_ * T_ * V_;

    const int SMEM_EA   = (128 * 257 + 16 * 128) * 4;                    // 139776 B
    const int SMEM_LOOP = (64 * 132 + 16 * 133 + 4096 + 64) * 4;         // 58944 B
    static bool attr_done = false;
    if (!attr_done) {
        cudaFuncSetAttribute(k_enc_att, cudaFuncAttributeMaxDynamicSharedMemorySize, SMEM_EA);
        cudaFuncSetAttribute(k_loop, cudaFuncAttributeMaxDynamicSharedMemorySize, SMEM_LOOP);
        attr_done = true;
    }

    k_enc_bf<<<(B_ * V_ * ENC_) / 4 / 256, 256>>>(enc);
    k_enc_att<<<(B_ * V_) / 16, 256, SMEM_EA>>>(enc, W_enc, b_enc);
    k_mean<<<B_, 512>>>(enc);
    k_init<<<B_, 512>>>(W_init_h, b_init_h, W_init_c, b_init_c,
                        W_dec, b_dec, W_beta, b_beta, caps, emb_W);
    k_loop<<<GRID_, NTHR_, SMEM_LOOP>>>(lens, caps, emb_W, w_full, b_full,
                                        W_ih, W_hh, b_ih, b_hh,
                                        W_dec, b_dec, W_beta, b_beta,
                                        W_final, b_final, out_pred, out_alpha);
    k_reset<<<1, 512>>>(lens, out_lens);
}

// round 13
// speedup vs baseline: 1.1498x; 1.0371x over previous
#include <cuda_runtime.h>
#include <cuda_bf16.h>
#include <cstdint>

#define B_    64
#define V_    2048
#define ENC_  128
#define T_    100
#define EMB_  256
#define DEC_  512
#define ATT_  256
#define VOC_  29
#define XDIM_ 896   // EMB + ENC + DEC
#define NROW_ 413   // 256 dec_att + 128 gate + 29 pred

#define GRID_ 148
#define NTHR_ 1024

// ---------------- scratch ----------------
__device__ __nv_bfloat16 g_enc_att_bf[(size_t)B_ * V_ * ATT_];   // 67 MB
__device__ __nv_bfloat16 g_enc_bf[(size_t)B_ * V_ * ENC_];       // 33.5 MB
__device__ float g_mean[B_ * ENC_];
__device__ float g_h[B_ * DEC_];     // masked h (carry)
__device__ float g_hn[B_ * DEC_];    // raw h_new (for pred)
__device__ float g_c[B_ * DEC_];
__device__ float g_dec_att[B_ * ATT_];
__device__ float g_gate[B_ * ENC_];
__device__ float g_scores[B_ * V_];
__device__ float g_x[B_ * XDIM_];                      // [emb | gated awe | h]
__device__ float g_gates_p[2][B_ * 4 * DEC_];          // split-K partials
__device__ float g_awe_p[B_ * 4 * ENC_];               // per-chunk awe partials
__device__ unsigned g_cnt[B_];                         // wraps each step (atomicInc 3u)
__device__ unsigned g_flags[GRID_];                    // per-CTA barrier flags

__device__ __forceinline__ float sigm(float x) { return 1.0f / (1.0f + __expf(-x)); }

// distributed-flag grid barrier: own-slot atomicExch arrival (parallel),
// warp0 acquire-polls all flags, monotonic tags (no reset during run)
__device__ __forceinline__ void gridbar(unsigned tag) {
    __syncthreads();
    if (threadIdx.x == 0) {
        __threadfence();                               // release prior writes
        atomicExch(&g_flags[blockIdx.x], tag);         // distinct address per CTA
    }
    if (threadIdx.x < 32) {
        long long guard = 0;
        bool done = false;
        do {
            bool ok = true;
            for (int i = threadIdx.x; i < GRID_; i += 32) {
                unsigned v;
                asm volatile("ld.acquire.gpu.u32 %0, [%1];" : "=r"(v) : "l"(&g_flags[i]));
                ok &= (v >= tag);
            }
            done = __all_sync(0xFFFFFFFFu, ok);
            if (!done) __nanosleep(16);
        } while (!done && ++guard < (1LL << 30));
        if (threadIdx.x == 0) __threadfence();         // acquire; fresh L1
    }
    __syncthreads();
}

// ---------------- prologue kernels (run once, outside the loop) ----------------
__global__ void k_enc_bf(const float* __restrict__ enc) {
    size_t i = (size_t)blockIdx.x * blockDim.x + threadIdx.x;
    const float4* in = (const float4*)enc;
    float4 v = in[i];
    __nv_bfloat162* out = (__nv_bfloat162*)g_enc_bf;
    out[i * 2]     = __floats2bfloat162_rn(v.x, v.y);
    out[i * 2 + 1] = __floats2bfloat162_rn(v.z, v.w);
}

__global__ void k_enc_att(const float* __restrict__ enc,
                          const float* __restrict__ W_enc,
                          const float* __restrict__ b_enc) {
    extern __shared__ float sm[];
    float* sWT = sm;                 // [128][257]
    float* sE  = sm + 128 * 257;     // [16][128]
    int tid = threadIdx.x;
    for (int idx = tid; idx < ATT_ * ENC_; idx += 256) {
        int a = idx >> 7, e = idx & 127;
        sWT[e * 257 + a] = W_enc[idx];
    }
    int row0 = blockIdx.x * 16;
    for (int idx = tid; idx < 16 * ENC_; idx += 256) {
        int r = idx >> 7, e = idx & 127;
        sE[r * ENC_ + e] = enc[(size_t)(row0 + r) * ENC_ + e];
    }
    __syncthreads();
    int a = tid;
    float bb = b_enc[a];
    float acc[16];
#pragma unroll
    for (int r = 0; r < 16; r++) acc[r] = bb;
    for (int e = 0; e < ENC_; e++) {
        float w = sWT[e * 257 + a];
#pragma unroll
        for (int r = 0; r < 16; r++) acc[r] = fmaf(sE[r * ENC_ + e], w, acc[r]);
    }
#pragma unroll
    for (int r = 0; r < 16; r++)
        g_enc_att_bf[(size_t)(row0 + r) * ATT_ + a] = __float2bfloat16(acc[r]);
}

__global__ void k_mean(const float* __restrict__ enc) {
    int b = blockIdx.x, tid = threadIdx.x;
    int g = tid >> 7, e = tid & 127;
    const float* base = enc + ((size_t)b * V_ + g * 512) * ENC_ + e;
    float s = 0.f;
#pragma unroll 8
    for (int v = 0; v < 512; v++) s += base[(size_t)v * ENC_];
    __shared__ float sp[4][128];
    sp[g][e] = s;
    __syncthreads();
    if (tid < 128)
        g_mean[b * ENC_ + tid] = (sp[0][tid] + sp[1][tid] + sp[2][tid] + sp[3][tid]) * (1.0f / V_);
}

__device__ __forceinline__ void attention_pre(int b, int tid, const float* sh,
                                              const float* __restrict__ W_dec,
                                              const float* __restrict__ b_dec,
                                              const float* __restrict__ W_beta,
                                              const float* __restrict__ b_beta) {
    const float4* h4 = (const float4*)sh;
    if (tid < ATT_) {
        float acc = b_dec[tid];
        const float4* w = (const float4*)(W_dec + tid * DEC_);
#pragma unroll 8
        for (int k = 0; k < DEC_ / 4; k++) {
            float4 a = w[k]; float4 h = h4[k];
            acc += a.x * h.x + a.y * h.y + a.z * h.z + a.w * h.w;
        }
        g_dec_att[b * ATT_ + tid] = acc;
    } else if (tid < ATT_ + ENC_) {
        int e = tid - ATT_;
        float acc = b_beta[e];
        const float4* w = (const float4*)(W_beta + e * DEC_);
#pragma unroll 8
        for (int k = 0; k < DEC_ / 4; k++) {
            float4 a = w[k]; float4 h = h4[k];
            acc += a.x * h.x + a.y * h.y + a.z * h.z + a.w * h.w;
        }
        g_gate[b * ENC_ + e] = sigm(acc);
    }
}

__global__ void k_init(const float* __restrict__ Wh, const float* __restrict__ bh,
                       const float* __restrict__ Wc, const float* __restrict__ bc,
                       const float* __restrict__ W_dec, const float* __restrict__ b_dec,
                       const float* __restrict__ W_beta, const float* __restrict__ b_beta,
                       const int* __restrict__ caps, const float* __restrict__ emb_W) {
    int b = blockIdx.x, tid = threadIdx.x;
    __shared__ float smn[ENC_];
    __shared__ float sh[DEC_];
    if (tid < ENC_) smn[tid] = g_mean[b * ENC_ + tid];
    __syncthreads();
    {
        int d = tid;
        float ah = bh[d], ac = bc[d];
        const float4* wrh = (const float4*)(Wh + d * ENC_);
        const float4* wrc = (const float4*)(Wc + d * ENC_);
        const float4* mv  = (const float4*)smn;
#pragma unroll 8
        for (int k = 0; k < ENC_ / 4; k++) {
            float4 m4 = mv[k]; float4 h4 = wrh[k]; float4 c4 = wrc[k];
            ah += m4.x * h4.x + m4.y * h4.y + m4.z * h4.z + m4.w * h4.w;
            ac += m4.x * c4.x + m4.y * c4.y + m4.z * c4.z + m4.w * c4.w;
        }
        g_h[b * DEC_ + d] = ah;
        g_c[b * DEC_ + d] = ac;
        g_x[b * XDIM_ + EMB_ + ENC_ + d] = ah;
        sh[d] = ah;
    }
    if (tid < 256) {
        int cap = caps[b * T_];
        g_x[b * XDIM_ + tid] = emb_W[cap * EMB_ + tid];
    }
    __syncthreads();
    attention_pre(b, tid, sh, W_dec, b_dec, W_beta, b_beta);
}

// ---------------- the persistent loop kernel (R6 champion phases, verbatim) ----------------
__global__ void __launch_bounds__(NTHR_, 1)
k_loop(const int* __restrict__ lens, const int* __restrict__ caps,
       const float* __restrict__ emb_W,
       const float* __restrict__ w_full, const float* __restrict__ b_full,
       const float* __restrict__ W_ih, const float* __restrict__ W_hh,
       const float* __restrict__ b_ih, const float* __restrict__ b_hh,
       const float* __restrict__ W_dec, const float* __restrict__ b_dec,
       const float* __restrict__ W_beta, const float* __restrict__ b_beta,
       const float* __restrict__ W_final, const float* __restrict__ b_final,
       float* __restrict__ out_pred, float* __restrict__ out_alpha)
{
    extern __shared__ float sm[];
    __shared__ bool sflag;
    const int cta = blockIdx.x, tid = threadIdx.x;
    const int warp = tid >> 5, lane = tid & 31;
    unsigned bs = 1;

    for (int t = 0; t < T_; t++) {
        // ===== Phase A: scores; tasks = 64b x 8 vblocks(256 v) =====
        {
            float* sda = sm;           // [256]
            float* sw  = sm + 256;     // [256]
            float bf = b_full[0];
            for (int task = cta; task < 512; task += GRID_) {
                int b = task >> 3;
                int v0 = (task & 7) * 256;
                __syncthreads();
                if (tid < 256) sda[tid] = g_dec_att[b * ATT_ + tid];
                else if (tid < 512) sw[tid - 256] = w_full[tid - 256];
                __syncthreads();
#pragma unroll
                for (int r = 0; r < 8; r++) {
                    int v = v0 + warp * 8 + r;
                    const __nv_bfloat162* row =
                        (const __nv_bfloat162*)(g_enc_att_bf + (size_t)(b * V_ + v) * ATT_);
                    float acc = 0.f;
#pragma unroll
                    for (int k = 0; k < 4; k++) {
                        int a2 = lane + k * 32;
                        float2 e2 = __bfloat1622float2(row[a2]);
                        int a = a2 * 2;
                        acc += fmaxf(e2.x + sda[a], 0.f) * sw[a]
                             + fmaxf(e2.y + sda[a + 1], 0.f) * sw[a + 1];
                    }
#pragma unroll
                    for (int o = 16; o; o >>= 1) acc += __shfl_xor_sync(0xFFFFFFFFu, acc, o);
                    if (lane == 0) g_scores[b * V_ + v] = acc + bf;
                }
            }
        }
        gridbar(bs++);

        // ===== Phase B: softmax + alpha out + awe partials (+last-CTA combine) =====
        {
            float* s_al = sm;            // [512]
            float* red  = sm + 512;      // [32]
            float* part = sm + 544;      // [8][128]
            for (int task = cta; task < 256; task += GRID_) {
                int b = task >> 2, g = task & 3;
                __syncthreads();
                float sc0 = g_scores[b * V_ + tid];
                float sc1 = g_scores[b * V_ + tid + 1024];
                float mx = fmaxf(sc0, sc1);
#pragma unroll
                for (int o = 16; o; o >>= 1) mx = fmaxf(mx, __shfl_xor_sync(0xFFFFFFFFu, mx, o));
                if (lane == 0) red[warp] = mx;
                __syncthreads();
                if (tid < 32) {
                    float m2 = red[tid];
#pragma unroll
                    for (int o = 16; o; o >>= 1) m2 = fmaxf(m2, __shfl_xor_sync(0xFFFFFFFFu, m2, o));
                    if (tid == 0) red[0] = m2;
                }
                __syncthreads();
                mx = red[0];
                float e0 = __expf(sc0 - mx), e1 = __expf(sc1 - mx);
                float se = e0 + e1;
#pragma unroll
                for (int o = 16; o; o >>= 1) se += __shfl_xor_sync(0xFFFFFFFFu, se, o);
                __syncthreads();
                if (lane == 0) red[warp] = se;
                __syncthreads();
                if (tid < 32) {
                    float s2 = red[tid];
#pragma unroll
                    for (int o = 16; o; o >>= 1) s2 += __shfl_xor_sync(0xFFFFFFFFu, s2, o);
                    if (tid == 0) red[0] = s2;
                }
                __syncthreads();
                float inv = 1.0f / red[0];
                bool msk = t < lens[b];
                int half = g & 1;
                int i_sel = g >> 1;
                int owner = (tid >> 9) == half;
                if (owner) {
                    int sv = tid - half * 512;
                    float ex = i_sel ? e1 : e0;
                    float al = ex * inv;
                    s_al[sv] = al;
                    out_alpha[(size_t)(b * T_ + t) * V_ + g * 512 + sv] = msk ? al : 0.f;
                }
                __syncthreads();
                int sub = tid >> 7, e = tid & 127;
                const __nv_bfloat16* base =
                    g_enc_bf + ((size_t)b * V_ + g * 512 + sub * 64) * ENC_ + e;
                const float* ap = s_al + sub * 64;
                float s = 0.f;
#pragma unroll 8
                for (int v = 0; v < 64; v++) s += ap[v] * __bfloat162float(base[(size_t)v * ENC_]);
                part[sub * 128 + e] = s;
                __syncthreads();
                if (tid < 128) {
                    float tot = 0.f;
#pragma unroll
                    for (int k = 0; k < 8; k++) tot += part[k * 128 + tid];
                    g_awe_p[(b * 4 + g) * ENC_ + tid] = tot;
                }
                __threadfence();
                __syncthreads();
                if (tid == 0) {
                    unsigned v = atomicInc(&g_cnt[b], 3u);
                    sflag = (v == 3u);
                }
                __syncthreads();
                if (sflag) {
                    __threadfence();
                    if (tid < 128) {
                        float tot = g_awe_p[(b * 4 + 0) * ENC_ + tid]
                                  + g_awe_p[(b * 4 + 1) * ENC_ + tid]
                                  + g_awe_p[(b * 4 + 2) * ENC_ + tid]
                                  + g_awe_p[(b * 4 + 3) * ENC_ + tid];
                        g_x[b * XDIM_ + EMB_ + tid] = tot * g_gate[b * ENC_ + tid];
                    }
                }
            }
        }
        gridbar(bs++);

        // ===== Phase C: gates GEMM, tasks = (jt 0..127, slab 0..1) =====
        {
            float* sX  = sm;                       // [64][132]
            float* sW  = sm + 64 * 132;            // [16][133]
            float* red = sW + 16 * 133;            // [4096]
            int jj = tid & 15, bq = (tid >> 4) & 15, ks = tid >> 8;
            for (int task = cta; task < 256; task += GRID_) {
                int slab = task >> 7;
                int j0 = (task & 127) * 16;
                const float* src = slab ? W_hh : W_ih;
                int ld  = slab ? DEC_ : 384;
                int kx0 = slab ? 384 : 0;
                int nch = slab ? 4 : 3;
                float acc[4] = {0.f, 0.f, 0.f, 0.f};
                for (int kc = 0; kc < nch; kc++) {
                    int k0 = kc * 128;
                    __syncthreads();
#pragma unroll
                    for (int r = 0; r < 8; r++) {
                        int idx = tid + r * 1024;
                        int bb = idx >> 7, kk = idx & 127;
                        sX[bb * 132 + kk] = g_x[bb * XDIM_ + kx0 + k0 + kk];
                    }
#pragma unroll
                    for (int r = 0; r < 2; r++) {
                        int e2 = tid + r * 1024;
                        int j2 = e2 >> 7, kk = e2 & 127;
                        sW[j2 * 133 + kk] = src[(j0 + j2) * ld + k0 + kk];
                    }
                    __syncthreads();
                    const float* wrow = sW + jj * 133 + ks * 32;
#pragma unroll
                    for (int kk = 0; kk < 32; kk++) {
                        float w = wrow[kk];
#pragma unroll
                        for (int i = 0; i < 4; i++)
                            acc[i] = fmaf(sX[(bq * 4 + i) * 132 + ks * 32 + kk], w, acc[i]);
                    }
                }
                __syncthreads();
#pragma unroll
                for (int i = 0; i < 4; i++)
                    red[(ks * 256 + bq * 16 + jj) * 4 + i] = acc[i];
                __syncthreads();
                {
                    int jr = tid & 15, br = (tid >> 4) & 15, ir = tid >> 8;
                    float s = red[(0 * 256 + br * 16 + jr) * 4 + ir]
                            + red[(1 * 256 + br * 16 + jr) * 4 + ir]
                            + red[(2 * 256 + br * 16 + jr) * 4 + ir]
                            + red[(3 * 256 + br * 16 + jr) * 4 + ir];
                    int b = br * 4 + ir;
                    g_gates_p[slab][b * (4 * DEC_) + j0 + jr] = s;
                }
            }
        }
        gridbar(bs++);

        // ===== Phase D: LSTM cell (elementwise) + emb prefetch =====
        if (cta < B_) {
            int b = cta;
            if (tid < DEC_) {
                int base = b * 4 * DEC_;
                float gi = g_gates_p[0][base + tid]            + g_gates_p[1][base + tid]
                         + b_ih[tid]            + b_hh[tid];
                float gf = g_gates_p[0][base + DEC_ + tid]     + g_gates_p[1][base + DEC_ + tid]
                         + b_ih[DEC_ + tid]     + b_hh[DEC_ + tid];
                float gg = g_gates_p[0][base + 2 * DEC_ + tid] + g_gates_p[1][base + 2 * DEC_ + tid]
                         + b_ih[2 * DEC_ + tid] + b_hh[2 * DEC_ + tid];
                float go = g_gates_p[0][base + 3 * DEC_ + tid] + g_gates_p[1][base + 3 * DEC_ + tid]
                         + b_ih[3 * DEC_ + tid] + b_hh[3 * DEC_ + tid];
                float ig = sigm(gi), fg = sigm(gf), og = sigm(go);
                float gt = tanhf(gg);
                float c_old = g_c[b * DEC_ + tid];
                float cn = fg * c_old + ig * gt;
                float hn = og * tanhf(cn);
                bool msk = t < lens[b];
                float h_old = g_h[b * DEC_ + tid];
                float h2 = msk ? hn : h_old;
                float c2 = msk ? cn : c_old;
                g_h[b * DEC_ + tid] = h2;
                g_c[b * DEC_ + tid] = c2;
                g_hn[b * DEC_ + tid] = hn;
                g_x[b * XDIM_ + EMB_ + ENC_ + tid] = h2;
            } else if (tid < DEC_ + EMB_ && t + 1 < T_) {
                int e = tid - DEC_;
                int cap = caps[b * T_ + t + 1];
                g_x[b * XDIM_ + e] = emb_W[cap * EMB_ + e];
            }
        }
        gridbar(bs++);

        // ===== Phase E: dec_att / gate / pred — [413x512] @ h, tasks of 4 rows =====
        {
            float* red = sm;                 // [4 rr][4 ks][64 b]
            int rr = tid >> 8, ks = (tid >> 6) & 3, b = tid & 63;
            for (int task = cta; task < 104; task += GRID_) {
                int r0 = task * 4;
                int j = r0 + rr;
                float acc = 0.f;
                __syncthreads();
                if (j < NROW_) {
                    const float* W;
                    if (j < 256)      W = W_dec   + j * DEC_;
                    else if (j < 384) W = W_beta  + (j - 256) * DEC_;
                    else              W = W_final + (j - 384) * DEC_;
                    const float* H = (j < 384) ? g_h : g_hn;
                    const float4* w4 = (const float4*)(W) + ks * 32;
                    const float4* h4 = (const float4*)(H + b * DEC_) + ks * 32;
#pragma unroll 8
                    for (int k = 0; k < 32; k++) {
                        float4 w = w4[k]; float4 x = h4[k];
                        acc += w.x * x.x + w.y * x.y + w.z * x.z + w.w * x.w;
                    }
                }
                red[(rr * 4 + ks) * 64 + b] = acc;
                __syncthreads();
                if (tid < 256) {
                    int rr2 = tid >> 6, b2 = tid & 63;
                    int j2 = r0 + rr2;
                    if (j2 < NROW_) {
                        float s = red[(rr2 * 4 + 0) * 64 + b2] + red[(rr2 * 4 + 1) * 64 + b2]
                                + red[(rr2 * 4 + 2) * 64 + b2] + red[(rr2 * 4 + 3) * 64 + b2];
                        if (j2 < 256)
                            g_dec_att[b2 * ATT_ + j2] = s + b_dec[j2];
                        else if (j2 < 384)
                            g_gate[b2 * ENC_ + (j2 - 256)] = sigm(s + b_beta[j2 - 256]);
                        else {
                            bool msk = t < lens[b2];
                            out_pred[(size_t)(b2 * T_ + t) * VOC_ + (j2 - 384)] =
                                msk ? (s + b_final[j2 - 384]) : 0.f;
                        }
                    }
                }
            }
        }
        gridbar(bs++);
    }
}

__global__ void k_reset(const int* __restrict__ lens, float* __restrict__ out_lens) {
    int i = threadIdx.x;
    if (i < GRID_) g_flags[i] = 0;
    if (i < B_) { g_cnt[i] = 0; out_lens[i] = (float)lens[i]; }
}

// ---------------- launch ----------------
extern "C" void kernel_launch(void* const* d_in, const int* in_sizes, int n_in,
                              void* d_out, int out_size) {
    const float* enc      = (const float*)d_in[0];
    const int*   caps     = (const int*)  d_in[1];
    const int*   lens     = (const int*)  d_in[2];
    const float* emb_W    = (const float*)d_in[3];
    const float* W_enc    = (const float*)d_in[4];
    const float* b_enc    = (const float*)d_in[5];
    const float* W_dec    = (const float*)d_in[6];
    const float* b_dec    = (const float*)d_in[7];
    const float* w_full   = (const float*)d_in[8];
    const float* b_full   = (const float*)d_in[9];
    const float* W_ih     = (const float*)d_in[10];
    const float* b_ih     = (const float*)d_in[11];
    const float* W_hh     = (const float*)d_in[12];
    const float* b_hh     = (const float*)d_in[13];
    const float* W_init_h = (const float*)d_in[14];
    const float* b_init_h = (const float*)d_in[15];
    const float* W_init_c = (const float*)d_in[16];
    const float* b_init_c = (const float*)d_in[17];
    const float* W_beta   = (const float*)d_in[18];
    const float* b_beta   = (const float*)d_in[19];
    const float* W_final  = (const float*)d_in[20];
    const float* b_final  = (const float*)d_in[21];

    float* out       = (float*)d_out;
    float* out_pred  = out;                                    // [B,T,VOC]
    float* out_alpha = out + (size_t)B_ * T_ * VOC_;           // [B,T,V]
    float* out_lens  = out_alpha + (size_t)B_ * T_ * V_;       // [B]

    const int SMEM_EA   = (128 * 257 + 16 * 128) * 4;          // 139776 B
    const int SMEM_LOOP = (64 * 132 + 16 * 133 + 4096) * 4;    // 58688 B
    static bool attr_done = false;
    if (!attr_done) {
        cudaFuncSetAttribute(k_enc_att, cudaFuncAttributeMaxDynamicSharedMemorySize, SMEM_EA);
        cudaFuncSetAttribute(k_loop, cudaFuncAttributeMaxDynamicSharedMemorySize, SMEM_LOOP);
        attr_done = true;
    }

    k_enc_bf<<<(B_ * V_ * ENC_) / 4 / 256, 256>>>(enc);
    k_enc_att<<<(B_ * V_) / 16, 256, SMEM_EA>>>(enc, W_enc, b_enc);
    k_mean<<<B_, 512>>>(enc);
    k_init<<<B_, 512>>>(W_init_h, b_init_h, W_init_c, b_init_c,
                        W_dec, b_dec, W_beta, b_beta, caps, emb_W);
    k_loop<<<GRID_, NTHR_, SMEM_LOOP>>>(lens, caps, emb_W, w_full, b_full,
                                        W_ih, W_hh, b_ih, b_hh,
                                        W_dec, b_dec, W_beta, b_beta,
                                        W_final, b_final, out_pred, out_alpha);
    k_reset<<<1, 512>>>(lens, out_lens);
}